// round 1
// baseline (speedup 1.0000x reference)
#include <cuda_runtime.h>
#include <cstdint>

#define TLEN   64
#define BATCH  32
#define MROWS  2048          // BATCH * TLEN (tlen-major rows)
#define DDIM   512
#define VOCAB  32000
#define SLEN   400
#define CVOCAB 100
#define OUTC   (VOCAB + CVOCAB)
#define PAD_IDX 1

// scratch (allocation-free rule: __device__ globals)
__device__ float g_pcopy[MROWS];
__device__ int   g_srcidx[SLEN * BATCH];

// ---------------------------------------------------------------------------
// p_copy[r] = sigmoid(hidden[r,:] . Wc + bc)   — one warp per row
// ---------------------------------------------------------------------------
__global__ void pcopy_kernel(const float* __restrict__ hidden,
                             const float* __restrict__ Wc,
                             const float* __restrict__ bc) {
    int gw   = (blockIdx.x * blockDim.x + threadIdx.x) >> 5;
    int lane = threadIdx.x & 31;
    if (gw >= MROWS) return;
    const float* h = hidden + (size_t)gw * DDIM;
    float s = 0.f;
    #pragma unroll 4
    for (int k = lane; k < DDIM; k += 32) s += h[k] * Wc[k];
    #pragma unroll
    for (int o = 16; o > 0; o >>= 1) s += __shfl_xor_sync(0xffffffffu, s, o);
    if (lane == 0) g_pcopy[gw] = 1.f / (1.f + __expf(-(s + bc[0])));
}

// ---------------------------------------------------------------------------
// Recover integer index from one-hot src_map[s, b, :]  (one thread per (s,b))
// ---------------------------------------------------------------------------
__global__ void srcidx_kernel(const float* __restrict__ src_map) {
    int i = blockIdx.x * blockDim.x + threadIdx.x;
    if (i >= SLEN * BATCH) return;
    const float* p = src_map + (size_t)i * CVOCAB;
    int idx = 0;
    for (int c = 0; c < CVOCAB; c++) {
        if (p[c] > 0.5f) { idx = c; break; }
    }
    g_srcidx[i] = idx;
}

// ---------------------------------------------------------------------------
// logits GEMM: C[r, n] = hidden[r,:] . W[:, n] + b[n]
// A: [2048, 512] row-major; B(W): [512, 32000] row-major; C stride OUTC.
// 128x128 tile, BK=16, 256 threads, 8x8 micro-tile in two 4-wide halves
// (conflict-free float4 shared loads).
// ---------------------------------------------------------------------------
__global__ __launch_bounds__(256) void gemm_logits(
    const float* __restrict__ A, const float* __restrict__ B,
    const float* __restrict__ bias, float* __restrict__ C) {

    __shared__ float As[16][128];
    __shared__ float Bs[16][128];

    const int bm  = blockIdx.y * 128;
    const int bn  = blockIdx.x * 128;
    const int tid = threadIdx.x;
    const int tx  = tid & 15;        // 16 col groups
    const int ty  = tid >> 4;        // 16 row groups

    // global-load mapping
    const int arow = tid >> 2;          // 0..63  (A rows, two passes: +0, +64)
    const int acol = (tid & 3) << 2;    // 0,4,8,12
    const int brow = tid >> 5;          // 0..7   (B rows, two passes: +0, +8)
    const int bcol = (tid & 31) << 2;   // 0..124

    float acc[8][8];
    #pragma unroll
    for (int i = 0; i < 8; i++)
        #pragma unroll
        for (int j = 0; j < 8; j++) acc[i][j] = 0.f;

    const float* Aptr = A + (size_t)(bm + arow) * DDIM + acol;
    const float* Bptr = B + (size_t)brow * VOCAB + bn + bcol;

    for (int k0 = 0; k0 < DDIM; k0 += 16) {
        float4 a0 = *(const float4*)(Aptr);
        float4 a1 = *(const float4*)(Aptr + (size_t)64 * DDIM);
        float4 b0 = *(const float4*)(Bptr);
        float4 b1 = *(const float4*)(Bptr + (size_t)8 * VOCAB);

        As[acol + 0][arow]      = a0.x;
        As[acol + 1][arow]      = a0.y;
        As[acol + 2][arow]      = a0.z;
        As[acol + 3][arow]      = a0.w;
        As[acol + 0][arow + 64] = a1.x;
        As[acol + 1][arow + 64] = a1.y;
        As[acol + 2][arow + 64] = a1.z;
        As[acol + 3][arow + 64] = a1.w;
        *(float4*)&Bs[brow][bcol]     = b0;
        *(float4*)&Bs[brow + 8][bcol] = b1;
        __syncthreads();

        #pragma unroll
        for (int k = 0; k < 16; k++) {
            float4 ra0 = *(const float4*)&As[k][ty * 4];
            float4 ra1 = *(const float4*)&As[k][64 + ty * 4];
            float4 rb0 = *(const float4*)&Bs[k][tx * 4];
            float4 rb1 = *(const float4*)&Bs[k][64 + tx * 4];
            float ra[8] = {ra0.x, ra0.y, ra0.z, ra0.w, ra1.x, ra1.y, ra1.z, ra1.w};
            float rb[8] = {rb0.x, rb0.y, rb0.z, rb0.w, rb1.x, rb1.y, rb1.z, rb1.w};
            #pragma unroll
            for (int i = 0; i < 8; i++)
                #pragma unroll
                for (int j = 0; j < 8; j++)
                    acc[i][j] += ra[i] * rb[j];
        }
        __syncthreads();

        Aptr += 16;
        Bptr += (size_t)16 * VOCAB;
    }

    // epilogue: logits + bias, written into the first VOCAB cols of d_out
    #pragma unroll
    for (int i = 0; i < 8; i++) {
        int row = bm + (i >> 2) * 64 + ty * 4 + (i & 3);
        float* crow = C + (size_t)row * OUTC;
        #pragma unroll
        for (int jc = 0; jc < 2; jc++) {
            int col = bn + jc * 64 + tx * 4;
            float4 bv = *(const float4*)&bias[col];
            float4 o;
            o.x = acc[i][jc * 4 + 0] + bv.x;
            o.y = acc[i][jc * 4 + 1] + bv.y;
            o.z = acc[i][jc * 4 + 2] + bv.z;
            o.w = acc[i][jc * 4 + 3] + bv.w;
            *(float4*)&crow[col] = o;
        }
    }
}

// ---------------------------------------------------------------------------
// Per-row softmax over VOCAB logits (in-place in d_out), PAD masked,
// scaled by (1 - p_copy).  One CTA (256 threads) per row; online max/sum.
// ---------------------------------------------------------------------------
__global__ __launch_bounds__(256) void softmax_kernel(float* __restrict__ out) {
    const int r   = blockIdx.x;
    const int tid = threadIdx.x;
    float* row = out + (size_t)r * OUTC;

    float m = -INFINITY, s = 0.f;
    for (int c = tid; c < VOCAB; c += 256) {
        if (c == PAD_IDX) continue;
        float v = row[c];
        if (v > m) {
            s = s * __expf(m - v) + 1.f;
            m = v;
        } else {
            s += __expf(v - m);
        }
    }

    // warp reduce (m, s) pairs
    #pragma unroll
    for (int o = 16; o > 0; o >>= 1) {
        float mo = __shfl_xor_sync(0xffffffffu, m, o);
        float so = __shfl_xor_sync(0xffffffffu, s, o);
        float M2 = fmaxf(m, mo);
        s = s * __expf(m - M2) + so * __expf(mo - M2);
        m = M2;
    }

    __shared__ float smM[8], smS[8];
    const int wid = tid >> 5, lane = tid & 31;
    if (lane == 0) { smM[wid] = m; smS[wid] = s; }
    __syncthreads();
    if (wid == 0) {
        m = (lane < 8) ? smM[lane] : -INFINITY;
        s = (lane < 8) ? smS[lane] : 0.f;
        #pragma unroll
        for (int o = 4; o > 0; o >>= 1) {
            float mo = __shfl_xor_sync(0xffffffffu, m, o);
            float so = __shfl_xor_sync(0xffffffffu, s, o);
            float M2 = fmaxf(m, mo);
            s = s * __expf(m - M2) + so * __expf(mo - M2);
            m = M2;
        }
        if (lane == 0) { smM[0] = m; smS[0] = s; }
    }
    __syncthreads();

    const float M    = smM[0];
    const float scale = (1.f - g_pcopy[r]) / smS[0];

    for (int c = tid; c < VOCAB; c += 256) {
        row[c] = (c == PAD_IDX) ? 0.f : __expf(row[c] - M) * scale;
    }
}

// ---------------------------------------------------------------------------
// copy distribution: out[r, VOCAB + idx[s, b]] += attn[r, s] * p_copy[r]
// with b = r % BATCH. One CTA (128 threads) per row, smem atomics over 100 slots.
// ---------------------------------------------------------------------------
__global__ __launch_bounds__(128) void copy_kernel(const float* __restrict__ attn,
                                                   float* __restrict__ out) {
    const int r = blockIdx.x;
    const int b = r & (BATCH - 1);
    const int tid = threadIdx.x;

    __shared__ float acc[CVOCAB];
    for (int c = tid; c < CVOCAB; c += 128) acc[c] = 0.f;
    __syncthreads();

    const float pc = g_pcopy[r];
    const float* arow = attn + (size_t)r * SLEN;
    for (int s = tid; s < SLEN; s += 128) {
        atomicAdd(&acc[g_srcidx[s * BATCH + b]], arow[s] * pc);
    }
    __syncthreads();

    float* orow = out + (size_t)r * OUTC + VOCAB;
    for (int c = tid; c < CVOCAB; c += 128) orow[c] = acc[c];
}

// ---------------------------------------------------------------------------
extern "C" void kernel_launch(void* const* d_in, const int* in_sizes, int n_in,
                              void* d_out, int out_size) {
    const float* hidden  = (const float*)d_in[0];  // [2048, 512]
    const float* attn    = (const float*)d_in[1];  // [2048, 400]
    const float* src_map = (const float*)d_in[2];  // [400, 32, 100]
    const float* W       = (const float*)d_in[3];  // [512, 32000]
    const float* b       = (const float*)d_in[4];  // [32000]
    const float* Wc      = (const float*)d_in[5];  // [512]
    const float* bc      = (const float*)d_in[6];  // [1]
    float* out = (float*)d_out;                    // [2048, 32100]

    // p_copy: 2048 warps
    pcopy_kernel<<<(MROWS * 32 + 255) / 256, 256>>>(hidden, Wc, bc);
    // one-hot -> index
    srcidx_kernel<<<(SLEN * BATCH + 255) / 256, 256>>>(src_map);
    // logits (with bias) straight into d_out[:, :VOCAB]
    dim3 grid(VOCAB / 128, MROWS / 128);
    gemm_logits<<<grid, 256>>>(hidden, W, b, out);
    // in-place masked softmax * (1 - p_copy)
    softmax_kernel<<<MROWS, 256>>>(out);
    // scattered copy distribution into d_out[:, VOCAB:]
    copy_kernel<<<MROWS, 128>>>(attn, out);
}

// round 3
// speedup vs baseline: 2.6620x; 2.6620x over previous
#include <cuda_runtime.h>
#include <cstdint>

#define TLEN   64
#define BATCH  32
#define MROWS  2048
#define DDIM   512
#define VOCAB  32000
#define SLEN   400
#define CVOCAB 100
#define OUTC   (VOCAB + CVOCAB)
#define PAD_IDX 1

#define KBLKS   (DDIM / 8)       // 64 k8 blocks
#define MT16    (MROWS / 16)     // 128 m-tiles of 16 rows
#define N16     (VOCAB / 16)     // 2000 n-tiles of 16 cols

// ---------------- device scratch (allocation-free rule) ----------------
__device__ float g_Afrag[(size_t)MROWS * DDIM];     // [mt16][kblk][128]
__device__ float g_Wfrag[(size_t)VOCAB * DDIM];     // [n16][kblk][128]
__device__ float g_pcopy[MROWS];
__device__ int   g_srcidx[SLEN * BATCH];

// ---------------- helpers ----------------
__device__ __forceinline__ uint32_t smem_u32(const void* p) {
    uint32_t a;
    asm("{ .reg .u64 t; cvta.to.shared.u64 t, %1; cvt.u32.u64 %0, t; }" : "=r"(a) : "l"(p));
    return a;
}
__device__ __forceinline__ uint32_t to_tf32(float v) {
    uint32_t r;
    asm("cvt.rna.tf32.f32 %0, %1;" : "=r"(r) : "f"(v));
    return r;
}
__device__ __forceinline__ void cp_async16(uint32_t dst, const void* src) {
    asm volatile("cp.async.cg.shared.global [%0], [%1], 16;" :: "r"(dst), "l"(src));
}
#define CP_COMMIT() asm volatile("cp.async.commit_group;" ::: "memory")

__device__ __forceinline__ void mma_tf32(float* c, uint32_t a0, uint32_t a1,
                                         uint32_t a2, uint32_t a3,
                                         uint32_t b0, uint32_t b1) {
    asm volatile(
        "mma.sync.aligned.m16n8k8.row.col.f32.tf32.tf32.f32 "
        "{%0,%1,%2,%3}, {%4,%5,%6,%7}, {%8,%9}, {%0,%1,%2,%3};"
        : "+f"(c[0]), "+f"(c[1]), "+f"(c[2]), "+f"(c[3])
        : "r"(a0), "r"(a1), "r"(a2), "r"(a3), "r"(b0), "r"(b1));
}
__device__ __forceinline__ void lds128(uint32_t* r, uint32_t addr) {
    asm volatile("ld.shared.v4.b32 {%0,%1,%2,%3}, [%4];"
                 : "=r"(r[0]), "=r"(r[1]), "=r"(r[2]), "=r"(r[3]) : "r"(addr));
}

// ---------------- fragment precompute ----------------
// A_frag[((mt*KBLKS)+kb)*128 + lane*4 + r] = tf32(A[mt*16 + g + 8*(r&1)][kb*8 + tig + 4*(r>>1)])
__global__ __launch_bounds__(256) void afrag_kernel(const float* __restrict__ A) {
    const int w = threadIdx.x >> 5, lane = threadIdx.x & 31;
    const int p = blockIdx.x * 8 + w;               // mt*KBLKS + kb
    const int mt = p >> 6, kb = p & 63;
    const int g = lane >> 2, tig = lane & 3;
    float4 o;
    const float* a0 = A + (size_t)(mt * 16 + g) * DDIM + kb * 8 + tig;
    const float* a1 = A + (size_t)(mt * 16 + g + 8) * DDIM + kb * 8 + tig;
    o.x = __uint_as_float(to_tf32(a0[0]));
    o.y = __uint_as_float(to_tf32(a1[0]));
    o.z = __uint_as_float(to_tf32(a0[4]));
    o.w = __uint_as_float(to_tf32(a1[4]));
    *(float4*)(g_Afrag + (size_t)p * 128 + lane * 4) = o;
}

// W_frag[((n16*KBLKS)+kb)*128 + lane*4 + r]:
//   r=0: W[kb*8+tig    ][n16*16 + g]      r=1: W[kb*8+tig+4][n16*16 + g]
//   r=2: W[kb*8+tig    ][n16*16 + 8 + g]  r=3: W[kb*8+tig+4][n16*16 + 8 + g]
__global__ __launch_bounds__(256) void wfrag_kernel(const float* __restrict__ W) {
    const int w = threadIdx.x >> 5, lane = threadIdx.x & 31;
    const int p = blockIdx.x * 8 + w;               // n16*KBLKS + kb
    const int n16 = p >> 6, kb = p & 63;
    const int g = lane >> 2, tig = lane & 3;
    const float* r0 = W + (size_t)(kb * 8 + tig) * VOCAB + n16 * 16 + g;
    const float* r1 = W + (size_t)(kb * 8 + tig + 4) * VOCAB + n16 * 16 + g;
    float4 o;
    o.x = __uint_as_float(to_tf32(r0[0]));
    o.y = __uint_as_float(to_tf32(r1[0]));
    o.z = __uint_as_float(to_tf32(r0[8]));
    o.w = __uint_as_float(to_tf32(r1[8]));
    *(float4*)(g_Wfrag + (size_t)p * 128 + lane * 4) = o;
}

// ---------------- mma.sync tf32 GEMM ----------------
// block tile 128x128, 8 warps (2m x 4n), warp tile 64x32, BK=16 (2 k8 steps)
// smem: As [2 buf][2 k8][8 mt][128], Bs same for n16 -> 16KB + 16KB
#define SM_A 0
#define SM_B 16384
#define NITER 32

__global__ __launch_bounds__(256, 2) void gemm_mma(
    const float* __restrict__ bias, float* __restrict__ out)
{
    __shared__ float smem[8192];   // 32KB
    const uint32_t sbase = smem_u32(smem);
    const int tid = threadIdx.x;
    const int wid = tid >> 5, lane = tid & 31;
    const int g = lane >> 2, tig = lane & 3;
    const int wm = wid & 1;        // 0..1  (64 rows each)
    const int wn = wid >> 1;       // 0..3  (32 cols each)
    const int bm16 = blockIdx.y * 8;   // 8 m-tiles
    const int bn16 = blockIdx.x * 8;   // 8 n16-tiles

    float c[4][4][4];
    #pragma unroll
    for (int i = 0; i < 4; i++)
        #pragma unroll
        for (int j = 0; j < 4; j++)
            #pragma unroll
            for (int k = 0; k < 4; k++) c[i][j][k] = 0.f;

    // ---- async load of one BK=16 chunk into buffer `buf` ----
    auto load_chunk = [&](int buf, int kb0) {
        #pragma unroll
        for (int h = 0; h < 2; h++) {
            int f = h * 256 + tid;               // 0..511
            int t8 = f >> 6;                     // tile idx 0..7
            int kl = (f >> 5) & 1;
            int v  = f & 31;
            const float* srcA = g_Afrag + ((size_t)(bm16 + t8) * KBLKS + kb0 + kl) * 128 + v * 4;
            cp_async16(sbase + SM_A + buf * 8192 + (kl * 8 + t8) * 512 + v * 16, srcA);
            const float* srcB = g_Wfrag + ((size_t)(bn16 + t8) * KBLKS + kb0 + kl) * 128 + v * 4;
            cp_async16(sbase + SM_B + buf * 8192 + (kl * 8 + t8) * 512 + v * 16, srcB);
        }
    };

    load_chunk(0, 0);
    CP_COMMIT();

    for (int it = 0; it < NITER; ++it) {
        const int buf = it & 1;
        if (it + 1 < NITER) {
            load_chunk(buf ^ 1, (it + 1) * 2);
            CP_COMMIT();
            asm volatile("cp.async.wait_group 1;" ::: "memory");
        } else {
            asm volatile("cp.async.wait_group 0;" ::: "memory");
        }
        __syncthreads();

        #pragma unroll
        for (int k8 = 0; k8 < 2; ++k8) {
            uint32_t a[4][4], b[2][4];
            #pragma unroll
            for (int mt = 0; mt < 4; mt++)
                lds128(a[mt], sbase + SM_A + buf * 8192 + (k8 * 8 + wm * 4 + mt) * 512 + lane * 16);
            #pragma unroll
            for (int nt = 0; nt < 2; nt++)
                lds128(b[nt], sbase + SM_B + buf * 8192 + (k8 * 8 + wn * 2 + nt) * 512 + lane * 16);
            #pragma unroll
            for (int mt = 0; mt < 4; mt++)
                #pragma unroll
                for (int nt = 0; nt < 2; nt++) {
                    mma_tf32(c[mt][nt * 2 + 0], a[mt][0], a[mt][1], a[mt][2], a[mt][3],
                             b[nt][0], b[nt][1]);
                    mma_tf32(c[mt][nt * 2 + 1], a[mt][0], a[mt][1], a[mt][2], a[mt][3],
                             b[nt][2], b[nt][3]);
                }
        }
        __syncthreads();
    }

    // ---- epilogue: logits + bias into out[:, :VOCAB] ----
    #pragma unroll
    for (int mt = 0; mt < 4; mt++) {
        const int rbase = (bm16 + wm * 4 + mt) * 16;
        #pragma unroll
        for (int j = 0; j < 4; j++) {
            const int cbase = (bn16 + wn * 2) * 16 + j * 8 + tig * 2;
            const float2 bv = *(const float2*)&bias[cbase];
            float2 v0, v1;
            v0.x = c[mt][j][0] + bv.x; v0.y = c[mt][j][1] + bv.y;
            v1.x = c[mt][j][2] + bv.x; v1.y = c[mt][j][3] + bv.y;
            *(float2*)(out + (size_t)(rbase + g) * OUTC + cbase) = v0;
            *(float2*)(out + (size_t)(rbase + g + 8) * OUTC + cbase) = v1;
        }
    }
}

// ---------------- small kernels (round-1 proven) ----------------
__global__ void pcopy_kernel(const float* __restrict__ hidden,
                             const float* __restrict__ Wc,
                             const float* __restrict__ bc) {
    int gw = (blockIdx.x * blockDim.x + threadIdx.x) >> 5;
    int lane = threadIdx.x & 31;
    if (gw >= MROWS) return;
    const float* h = hidden + (size_t)gw * DDIM;
    float s = 0.f;
    #pragma unroll 4
    for (int k = lane; k < DDIM; k += 32) s += h[k] * Wc[k];
    #pragma unroll
    for (int o = 16; o > 0; o >>= 1) s += __shfl_xor_sync(0xffffffffu, s, o);
    if (lane == 0) g_pcopy[gw] = 1.f / (1.f + __expf(-(s + bc[0])));
}

__global__ void srcidx_kernel(const float* __restrict__ src_map) {
    int i = blockIdx.x * blockDim.x + threadIdx.x;
    if (i >= SLEN * BATCH) return;
    const float* p = src_map + (size_t)i * CVOCAB;
    int idx = 0;
    for (int c = 0; c < CVOCAB; c++)
        if (p[c] > 0.5f) { idx = c; break; }
    g_srcidx[i] = idx;
}

__global__ __launch_bounds__(256) void softmax_kernel(float* __restrict__ out) {
    const int r   = blockIdx.x;
    const int tid = threadIdx.x;
    float* row = out + (size_t)r * OUTC;

    float m = -INFINITY, s = 0.f;
    for (int c = tid; c < VOCAB; c += 256) {
        if (c == PAD_IDX) continue;
        float v = row[c];
        if (v > m) { s = s * __expf(m - v) + 1.f; m = v; }
        else       { s += __expf(v - m); }
    }
    #pragma unroll
    for (int o = 16; o > 0; o >>= 1) {
        float mo = __shfl_xor_sync(0xffffffffu, m, o);
        float so = __shfl_xor_sync(0xffffffffu, s, o);
        float M2 = fmaxf(m, mo);
        s = s * __expf(m - M2) + so * __expf(mo - M2);
        m = M2;
    }
    __shared__ float smM[8], smS[8];
    const int wid = tid >> 5, lane = tid & 31;
    if (lane == 0) { smM[wid] = m; smS[wid] = s; }
    __syncthreads();
    if (wid == 0) {
        m = (lane < 8) ? smM[lane] : -INFINITY;
        s = (lane < 8) ? smS[lane] : 0.f;
        #pragma unroll
        for (int o = 4; o > 0; o >>= 1) {
            float mo = __shfl_xor_sync(0xffffffffu, m, o);
            float so = __shfl_xor_sync(0xffffffffu, s, o);
            float M2 = fmaxf(m, mo);
            s = s * __expf(m - M2) + so * __expf(mo - M2);
            m = M2;
        }
        if (lane == 0) { smM[0] = m; smS[0] = s; }
    }
    __syncthreads();
    const float M = smM[0];
    const float scale = (1.f - g_pcopy[r]) / smS[0];
    for (int c = tid; c < VOCAB; c += 256)
        row[c] = (c == PAD_IDX) ? 0.f : __expf(row[c] - M) * scale;
}

__global__ __launch_bounds__(128) void copy_kernel(const float* __restrict__ attn,
                                                   float* __restrict__ out) {
    const int r = blockIdx.x;
    const int b = r & (BATCH - 1);
    const int tid = threadIdx.x;
    __shared__ float acc[CVOCAB];
    for (int c = tid; c < CVOCAB; c += 128) acc[c] = 0.f;
    __syncthreads();
    const float pc = g_pcopy[r];
    const float* arow = attn + (size_t)r * SLEN;
    for (int s = tid; s < SLEN; s += 128)
        atomicAdd(&acc[g_srcidx[s * BATCH + b]], arow[s] * pc);
    __syncthreads();
    float* orow = out + (size_t)r * OUTC + VOCAB;
    for (int c = tid; c < CVOCAB; c += 128) orow[c] = acc[c];
}

// ---------------- launch ----------------
extern "C" void kernel_launch(void* const* d_in, const int* in_sizes, int n_in,
                              void* d_out, int out_size) {
    const float* hidden  = (const float*)d_in[0];
    const float* attn    = (const float*)d_in[1];
    const float* src_map = (const float*)d_in[2];
    const float* W       = (const float*)d_in[3];
    const float* b       = (const float*)d_in[4];
    const float* Wc      = (const float*)d_in[5];
    const float* bc      = (const float*)d_in[6];
    float* out = (float*)d_out;

    afrag_kernel<<<MT16 * KBLKS / 8, 256>>>(hidden);
    wfrag_kernel<<<N16 * KBLKS / 8, 256>>>(W);
    pcopy_kernel<<<(MROWS * 32 + 255) / 256, 256>>>(hidden, Wc, bc);
    srcidx_kernel<<<(SLEN * BATCH + 255) / 256, 256>>>(src_map);
    gemm_mma<<<dim3(N16 / 8, MT16 / 8), 256>>>(b, out);
    softmax_kernel<<<MROWS, 256>>>(out);
    copy_kernel<<<MROWS, 128>>>(attn, out);
}